// round 8
// baseline (speedup 1.0000x reference)
#include <cuda_runtime.h>
#include <cstdint>

#define N_NODES 100000
#define N_EDGES 1000000
#define D 64
#define LATENT 32
#define OUT_DIM 64
#define CAP 64                     // max edges per node (Poisson λ=10; P(>64)≈0)
#define NB_BUCKET 3907             // ceil(1e6 / 256)
#define NB_NODE 1563               // ceil(100k / 64)
#define XS2_STRIDE 65              // float2 units; stride 130 words ≡ 2 mod 32

// Scratch (BSS-zeroed at load; B re-zeros g_cnti tiles it consumed each call)
__device__ int   g_cnti[N_NODES];
__device__ int   g_bucket[(size_t)N_NODES * CAP];   // 25.6 MB edge ids
__device__ float g_hpre[(size_t)N_NODES * LATENT];  // node_attr @ W1[0:64]
__device__ float g_G[64 * LATENT];                  // global @ W1[128:192] + b1

// ---------------------------------------------------------------------------
// f32x2 packed helpers (Blackwell FFMA2/FADD2 — only reachable via PTX)
// ---------------------------------------------------------------------------
__device__ __forceinline__ uint64_t pack2(float a, float b) {
    uint64_t r; asm("mov.b64 %0, {%1, %2};" : "=l"(r) : "f"(a), "f"(b)); return r;
}
__device__ __forceinline__ void unpack2(uint64_t v, float& a, float& b) {
    asm("mov.b64 {%0, %1}, %2;" : "=f"(a), "=f"(b) : "l"(v));
}
__device__ __forceinline__ void ffma2(uint64_t& acc, uint64_t x, uint64_t w) {
    asm("fma.rn.f32x2 %0, %1, %2, %0;" : "+l"(acc) : "l"(x), "l"(w));
}
__device__ __forceinline__ void fadd2(uint64_t& acc, uint64_t x) {
    asm("add.rn.f32x2 %0, %0, %1;" : "+l"(acc) : "l"(x));
}

// ---------------------------------------------------------------------------
// Kernel A: [bucket-build | node-proj | G]
// ---------------------------------------------------------------------------
__global__ __launch_bounds__(256)
void prep_kernel(const int* __restrict__ recv,
                 const float* __restrict__ node_attr,
                 const float* __restrict__ global_attr,
                 const float* __restrict__ W1,
                 const float* __restrict__ b1) {
    __shared__ __align__(16) uint32_t smem_u[6400];   // 25 KB union
    const int tid = threadIdx.x;

    if (blockIdx.x < NB_BUCKET) {
        // ===== bucket build: per-node edge-id lists =====
        int e = blockIdx.x * 256 + tid;
        if (e < N_EDGES) {
            int r = __ldg(&recv[e]);
            int pos = atomicAdd(&g_cnti[r], 1);
            if (pos < CAP) g_bucket[(size_t)r * CAP + pos] = e;
        }
        return;
    }

    if (blockIdx.x < NB_BUCKET + NB_NODE) {
        // ===== node projection: hpre[n][j] = node[n][0:64] . W1[0:64][j] =====
        float2* sW  = reinterpret_cast<float2*>(smem_u);           // 8 KB
        float2* xs2 = reinterpret_cast<float2*>(smem_u + 2048);    // 16.6 KB
        const int tile = (blockIdx.x - NB_BUCKET) * 64;
        const int lane = tid & 31, p = tid >> 5;

        for (int idx = tid; idx < 1024; idx += 256) {
            int k2 = idx >> 5, j = idx & 31;
            sW[idx] = make_float2(W1[(2 * k2) * LATENT + j],
                                  (float)W1[(2 * k2 + 1) * LATENT + j]);
        }
        const int kq = tid & 15, srow = tid >> 4;
        #pragma unroll
        for (int it = 0; it < 4; it++) {
            int nn = it * 16 + srow, n = tile + nn;
            float4 v = make_float4(0.f, 0.f, 0.f, 0.f);
            if (n < N_NODES)
                v = reinterpret_cast<const float4*>(node_attr)[(size_t)n * 16 + kq];
            xs2[(2 * kq + 0) * XS2_STRIDE + nn] = make_float2(v.x, v.y);
            xs2[(2 * kq + 1) * XS2_STRIDE + nn] = make_float2(v.z, v.w);
        }
        __syncthreads();

        uint64_t a2[8];
        #pragma unroll
        for (int i = 0; i < 8; i++) a2[i] = pack2(0.f, 0.f);
        #pragma unroll 4
        for (int k2 = 0; k2 < 32; k2++) {
            uint64_t w2 = *reinterpret_cast<const uint64_t*>(&sW[k2 * 32 + lane]);
            const uint64_t* xr =
                reinterpret_cast<const uint64_t*>(&xs2[k2 * XS2_STRIDE + p * 8]);
            #pragma unroll
            for (int i = 0; i < 8; i++) ffma2(a2[i], xr[i], w2);
        }
        #pragma unroll
        for (int i = 0; i < 8; i++) {
            float lo, hi; unpack2(a2[i], lo, hi);
            int n = tile + p * 8 + i;
            if (n < N_NODES) g_hpre[(size_t)n * LATENT + lane] = lo + hi;
        }
        return;
    }

    // ===== G[b][j] = b1[j] + global[b] . W1[128:192][j] =====
    {
        float* sg = reinterpret_cast<float*>(smem_u);            // 16 KB
        float* sw = reinterpret_cast<float*>(smem_u + 4096);     // 8 KB
        float* sb = reinterpret_cast<float*>(smem_u + 6144);
        for (int i = tid; i < (64 * D) / 4; i += 256)
            reinterpret_cast<float4*>(sg)[i] =
                reinterpret_cast<const float4*>(global_attr)[i];
        for (int i = tid; i < (D * LATENT) / 4; i += 256)
            reinterpret_cast<float4*>(sw)[i] =
                reinterpret_cast<const float4*>(W1 + 2 * D * LATENT)[i];
        if (tid < LATENT) sb[tid] = b1[tid];
        __syncthreads();

        const int j = tid & 31, r0 = (tid >> 5) * 8;
        float acc[8];
        #pragma unroll
        for (int i = 0; i < 8; i++) acc[i] = sb[j];
        #pragma unroll 8
        for (int k = 0; k < D; k++) {
            float w = sw[k * LATENT + j];
            #pragma unroll
            for (int i = 0; i < 8; i++)
                acc[i] = fmaf(sg[(r0 + i) * D + k], w, acc[i]);
        }
        #pragma unroll
        for (int i = 0; i < 8; i++) g_G[(r0 + i) * LATENT + j] = acc[i];
    }
}

// ---------------------------------------------------------------------------
// Kernel B: gather (4-node interleaved, high MLP) + mean + edge-half layer1
// (FFMA2) + relu + layer2. Block = 64 nodes, warp = 8 nodes.
// ---------------------------------------------------------------------------
__global__ __launch_bounds__(256)
void mlp_kernel(const float* __restrict__ edge_attr,
                const float* __restrict__ W1,
                const float* __restrict__ W2,
                const float* __restrict__ b2,
                const int* __restrict__ ng,
                float* __restrict__ out) {
    __shared__ __align__(16) float2 sW1b[1024];            // 8 KB, W1 rows 64..127
    __shared__ float sW2[LATENT * OUT_DIM];                // 8 KB
    __shared__ float sb2[OUT_DIM];
    __shared__ __align__(16) float2 xs2[32 * XS2_STRIDE];  // 16.6 KB (reused for h)

    const int tid = threadIdx.x;
    const int tile = blockIdx.x * 64;
    const int lane = tid & 31, p = tid >> 5;
    const int nbase = tile + p * 8;

    for (int idx = tid; idx < 1024; idx += 256) {
        int k2 = idx >> 5, j = idx & 31;
        sW1b[idx] = make_float2(W1[(D + 2 * k2) * LATENT + j],
                                (float)W1[(D + 2 * k2 + 1) * LATENT + j]);
    }
    for (int i = tid; i < LATENT * OUT_DIM; i += 256) sW2[i] = W2[i];
    if (tid < OUT_DIM) sb2[tid] = b2[tid];

    // ---- gather + mean: 2 passes x 4 interleaved nodes; lane = k-pair
    const uint64_t* ea = reinterpret_cast<const uint64_t*>(edge_attr);
    #pragma unroll
    for (int pass = 0; pass < 2; pass++) {
        int cnts[4], ia[4], ib[4];
        uint64_t acc[4];
        #pragma unroll
        for (int i = 0; i < 4; i++) {
            int n = nbase + pass * 4 + i;
            bool ok = (n < N_NODES);
            cnts[i] = ok ? min(__ldg(&g_cnti[n]), CAP) : 0;
            const int* brow = g_bucket + (size_t)n * CAP;
            ia[i] = ok ? __ldg(&brow[lane]) : 0;
            ib[i] = ok ? __ldg(&brow[lane + 32]) : 0;
            acc[i] = pack2(0.f, 0.f);
        }
        int maxc = max(max(cnts[0], cnts[1]), max(cnts[2], cnts[3]));
        #pragma unroll 2
        for (int t = 0; t < maxc; t++) {
            #pragma unroll
            for (int i = 0; i < 4; i++) {
                if (t < cnts[i]) {   // warp-uniform predicate
                    int e = (t < 32) ? __shfl_sync(0xffffffffu, ia[i], t)
                                     : __shfl_sync(0xffffffffu, ib[i], t - 32);
                    fadd2(acc[i], ea[(size_t)e * 32 + lane]);
                }
            }
        }
        #pragma unroll
        for (int i = 0; i < 4; i++) {
            float a, b; unpack2(acc[i], a, b);
            float inv = 1.0f / (float)max(cnts[i], 1);
            xs2[lane * XS2_STRIDE + p * 8 + pass * 4 + i] =
                make_float2(a * inv, b * inv);
        }
    }
    __syncthreads();

    // re-zero consumed counters (all bucket/cnt reads are done)
    if (tid < 64 && tile + tid < N_NODES) g_cnti[tile + tid] = 0;

    // ---- init accumulators: hpre + G
    uint64_t a2[8];
    #pragma unroll
    for (int i = 0; i < 8; i++) {
        int n = nbase + i;
        float init = 0.f;
        if (n < N_NODES) {
            int g = __ldg(&ng[n]);
            init = g_hpre[(size_t)n * LATENT + lane] + g_G[g * LATENT + lane];
        }
        a2[i] = pack2(init, 0.f);
    }

    // ---- edge-half of layer 1: FFMA2 over k-pairs
    #pragma unroll 4
    for (int k2 = 0; k2 < 32; k2++) {
        uint64_t w2 = *reinterpret_cast<const uint64_t*>(&sW1b[k2 * 32 + lane]);
        const uint64_t* xr =
            reinterpret_cast<const uint64_t*>(&xs2[k2 * XS2_STRIDE + p * 8]);
        #pragma unroll
        for (int i = 0; i < 8; i++) ffma2(a2[i], xr[i], w2);
    }
    __syncthreads();   // xs2 reads done; reuse as h buffer

    // ---- relu, park h j-major
    float* hs2 = reinterpret_cast<float*>(xs2);
    float h[8];
    #pragma unroll
    for (int i = 0; i < 8; i++) {
        float lo, hi; unpack2(a2[i], lo, hi);
        h[i] = fmaxf(lo + hi, 0.f);
    }
    #pragma unroll
    for (int q = 0; q < 4; q++)
        *reinterpret_cast<uint64_t*>(
            &hs2[lane * (2 * XS2_STRIDE) + p * 8 + 2 * q]) =
            pack2(h[2 * q], h[2 * q + 1]);
    __syncthreads();

    // ---- layer 2
    uint64_t o2[4][2];
    #pragma unroll
    for (int q = 0; q < 4; q++) {
        o2[q][0] = pack2(sb2[lane], sb2[lane]);
        o2[q][1] = pack2(sb2[lane + 32], sb2[lane + 32]);
    }
    #pragma unroll 4
    for (int j = 0; j < LATENT; j++) {
        float wa = sW2[j * OUT_DIM + lane];
        float wb = sW2[j * OUT_DIM + lane + 32];
        uint64_t w0 = pack2(wa, wa);
        uint64_t w1 = pack2(wb, wb);
        const uint64_t* hr =
            reinterpret_cast<const uint64_t*>(&hs2[j * (2 * XS2_STRIDE) + p * 8]);
        #pragma unroll
        for (int q = 0; q < 4; q++) {
            uint64_t x = hr[q];
            ffma2(o2[q][0], x, w0);
            ffma2(o2[q][1], x, w1);
        }
    }

    #pragma unroll
    for (int q = 0; q < 4; q++) {
        int n0 = nbase + 2 * q;
        float a0, c0, a1, c1;
        unpack2(o2[q][0], a0, c0);
        unpack2(o2[q][1], a1, c1);
        if (n0 < N_NODES) {
            out[(size_t)n0 * OUT_DIM + lane]      = a0;
            out[(size_t)n0 * OUT_DIM + lane + 32] = a1;
        }
        if (n0 + 1 < N_NODES) {
            out[(size_t)(n0 + 1) * OUT_DIM + lane]      = c0;
            out[(size_t)(n0 + 1) * OUT_DIM + lane + 32] = c1;
        }
    }
}

// ---------------------------------------------------------------------------
extern "C" void kernel_launch(void* const* d_in, const int* in_sizes, int n_in,
                              void* d_out, int out_size) {
    const float* node_attr   = (const float*)d_in[0];
    const float* edge_attr   = (const float*)d_in[1];
    const float* global_attr = (const float*)d_in[2];
    const float* W1          = (const float*)d_in[3];
    const float* b1          = (const float*)d_in[4];
    const float* W2          = (const float*)d_in[5];
    const float* b2          = (const float*)d_in[6];
    const int*   recv        = (const int*)d_in[7];
    const int*   ng          = (const int*)d_in[8];
    float* out = (float*)d_out;

    // A) bucket build + node projection + G
    prep_kernel<<<NB_BUCKET + NB_NODE + 1, 256>>>(recv, node_attr, global_attr,
                                                  W1, b1);

    // B) interleaved gather + mean + MLP (+ counter re-zero)
    mlp_kernel<<<(N_NODES + 63) / 64, 256>>>(edge_attr, W1, W2, b2, ng, out);
}

// round 10
// speedup vs baseline: 1.2929x; 1.2929x over previous
#include <cuda_runtime.h>
#include <cstdint>

#define N_NODES 100000
#define N_EDGES 1000000
#define D 64
#define LATENT 32
#define OUT_DIM 64
#define SC_BLOCKS 3907             // ceil(16M items / 4096)
#define NB_NODE 1563               // ceil(100k / 64)
#define XS2_STRIDE 65              // float2 units; 130 words ≡ 2 mod 32
#define TOTAL_ITEMS 16000000LL

// Scratch (BSS-zeroed at load; B re-zeros consumed tiles each call)
__device__ float g_sums[(size_t)N_NODES * D];       // 25.6 MB edge sums
__device__ float g_cnt[N_NODES];
__device__ float g_hpre[(size_t)N_NODES * LATENT];  // node_attr @ W1[0:64]
__device__ float g_G[64 * LATENT];                  // global @ W1[128:192] + b1

// ---------------------------------------------------------------------------
// f32x2 packed helpers (Blackwell FFMA2 — only reachable via PTX)
// ---------------------------------------------------------------------------
__device__ __forceinline__ uint64_t pack2(float a, float b) {
    uint64_t r; asm("mov.b64 %0, {%1, %2};" : "=l"(r) : "f"(a), "f"(b)); return r;
}
__device__ __forceinline__ void unpack2(uint64_t v, float& a, float& b) {
    asm("mov.b64 {%0, %1}, %2;" : "=f"(a), "=f"(b) : "l"(v));
}
__device__ __forceinline__ void ffma2(uint64_t& acc, uint64_t x, uint64_t w) {
    asm("fma.rn.f32x2 %0, %1, %2, %0;" : "+l"(acc) : "l"(x), "l"(w));
}
__device__ __forceinline__ void red_add_v4(float* dst, float4 v) {
    asm volatile("red.global.add.v4.f32 [%0], {%1, %2, %3, %4};"
                 :: "l"(dst), "f"(v.x), "f"(v.y), "f"(v.z), "f"(v.w) : "memory");
}

// ---------------------------------------------------------------------------
// Kernel A: [batched edge scatter | node-proj | G]  (8 KB smem -> reg-limited occ)
// ---------------------------------------------------------------------------
__global__ __launch_bounds__(256)
void scatter_kernel(const float* __restrict__ edge_attr,
                    const int* __restrict__ recv,
                    const float* __restrict__ node_attr,
                    const float* __restrict__ global_attr,
                    const float* __restrict__ W1,
                    const float* __restrict__ b1) {
    __shared__ float sW[2048];   // 8 KB weight tile (node-proj / G branches)
    __shared__ float sb[LATENT];
    const int tid = threadIdx.x;

    if (blockIdx.x < SC_BLOCKS) {
        // ===== edge scatter: 4096 items/block, 16/thread, unroll-4 batches =====
        const long long base = (long long)blockIdx.x * 4096 + tid;
        #pragma unroll
        for (int o = 0; o < 4; o++) {
            float4 v[4]; int rr[4]; bool ok[4]; int cc[4];
            #pragma unroll
            for (int u = 0; u < 4; u++) {
                long long it = base + (long long)(o * 4 + u) * 256;
                ok[u] = (it < TOTAL_ITEMS);
                int e = (int)(it >> 4);
                cc[u] = (int)(it & 15);
                if (ok[u]) {
                    v[u]  = __ldg(&reinterpret_cast<const float4*>(edge_attr)
                                      [(size_t)e * 16 + cc[u]]);
                    rr[u] = __ldg(&recv[e]);
                }
            }
            #pragma unroll
            for (int u = 0; u < 4; u++) {
                if (ok[u]) {
                    red_add_v4(g_sums + (size_t)rr[u] * D + cc[u] * 4, v[u]);
                    if (cc[u] == 0) atomicAdd(&g_cnt[rr[u]], 1.0f);
                }
            }
        }
        return;
    }

    if (blockIdx.x < SC_BLOCKS + NB_NODE) {
        // ===== node projection: hpre[n][j] = node[n][0:64] . W1[0:64][j] =====
        const int tile = (blockIdx.x - SC_BLOCKS) * 64;
        const int lane = tid & 31, p = tid >> 5;
        for (int i = tid; i < D * LATENT; i += 256) sW[i] = W1[i];
        __syncthreads();

        const int n0 = tile + p * 8;
        float acc[8] = {};
        #pragma unroll 4
        for (int k4 = 0; k4 < 16; k4++) {
            float w0 = sW[(4 * k4 + 0) * LATENT + lane];
            float w1 = sW[(4 * k4 + 1) * LATENT + lane];
            float w2 = sW[(4 * k4 + 2) * LATENT + lane];
            float w3 = sW[(4 * k4 + 3) * LATENT + lane];
            #pragma unroll
            for (int i = 0; i < 8; i++) {
                int n = n0 + i;
                if (n < N_NODES) {
                    float4 x = __ldg(&reinterpret_cast<const float4*>(node_attr)
                                         [(size_t)n * 16 + k4]);
                    acc[i] = fmaf(x.x, w0, acc[i]);
                    acc[i] = fmaf(x.y, w1, acc[i]);
                    acc[i] = fmaf(x.z, w2, acc[i]);
                    acc[i] = fmaf(x.w, w3, acc[i]);
                }
            }
        }
        #pragma unroll
        for (int i = 0; i < 8; i++) {
            int n = n0 + i;
            if (n < N_NODES) g_hpre[(size_t)n * LATENT + lane] = acc[i];
        }
        return;
    }

    // ===== G[b][j] = b1[j] + global[b] . W1[128:192][j] =====
    {
        const int lane = tid & 31;
        for (int i = tid; i < D * LATENT; i += 256)
            sW[i] = W1[2 * D * LATENT + i];
        if (tid < LATENT) sb[tid] = b1[tid];
        __syncthreads();

        const int r0 = (tid >> 5) * 8;
        float acc[8];
        #pragma unroll
        for (int i = 0; i < 8; i++) acc[i] = sb[lane];
        #pragma unroll 4
        for (int k4 = 0; k4 < 16; k4++) {
            float w0 = sW[(4 * k4 + 0) * LATENT + lane];
            float w1 = sW[(4 * k4 + 1) * LATENT + lane];
            float w2 = sW[(4 * k4 + 2) * LATENT + lane];
            float w3 = sW[(4 * k4 + 3) * LATENT + lane];
            #pragma unroll
            for (int i = 0; i < 8; i++) {
                float4 x = __ldg(&reinterpret_cast<const float4*>(global_attr)
                                     [(size_t)(r0 + i) * 16 + k4]);
                acc[i] = fmaf(x.x, w0, acc[i]);
                acc[i] = fmaf(x.y, w1, acc[i]);
                acc[i] = fmaf(x.z, w2, acc[i]);
                acc[i] = fmaf(x.w, w3, acc[i]);
            }
        }
        #pragma unroll
        for (int i = 0; i < 8; i++) g_G[(r0 + i) * LATENT + lane] = acc[i];
    }
}

// ---------------------------------------------------------------------------
// Kernel B: mean staging + edge-half layer1 (FFMA2) + relu + layer2 + re-zero.
// Block = 64-node tile; warp owns 8 nodes. Stride-65 conflict-free staging.
// ---------------------------------------------------------------------------
__global__ __launch_bounds__(256)
void mlp_kernel(const float* __restrict__ W1,
                const float* __restrict__ W2,
                const float* __restrict__ b2,
                const int* __restrict__ ng,
                float* __restrict__ out) {
    __shared__ __align__(16) float2 sW1b[1024];            // 8 KB, W1 rows 64..127
    __shared__ float sW2[LATENT * OUT_DIM];                // 8 KB
    __shared__ float sb2[OUT_DIM];
    __shared__ __align__(16) float2 xs2[32 * XS2_STRIDE];  // 16.6 KB (reused for h)

    const int tid = threadIdx.x;
    const int tile = blockIdx.x * 64;
    const int lane = tid & 31, p = tid >> 5;
    const int nbase = tile + p * 8;

    for (int idx = tid; idx < 1024; idx += 256) {
        int k2 = idx >> 5, j = idx & 31;
        sW1b[idx] = make_float2(W1[(D + 2 * k2) * LATENT + j],
                                (float)W1[(D + 2 * k2 + 1) * LATENT + j]);
    }
    for (int i = tid; i < LATENT * OUT_DIM; i += 256) sW2[i] = W2[i];
    if (tid < OUT_DIM) sb2[tid] = b2[tid];

    // init accumulators: lo = hpre + G, hi = 0
    uint64_t a2[8];
    #pragma unroll
    for (int i = 0; i < 8; i++) {
        int n = nbase + i;
        float init = 0.f;
        if (n < N_NODES) {
            int g = __ldg(&ng[n]);
            init = g_hpre[(size_t)n * LATENT + lane] + g_G[g * LATENT + lane];
        }
        a2[i] = pack2(init, 0.f);
    }

    // stage mean aggregated edges, interleaved-k float2 (stride 65 -> no conflicts)
    const int kq = tid & 15, srow = tid >> 4;
    #pragma unroll
    for (int it = 0; it < 4; it++) {
        int nn = it * 16 + srow, n = tile + nn;
        float4 v = make_float4(0.f, 0.f, 0.f, 0.f);
        if (n < N_NODES) {
            v = reinterpret_cast<const float4*>(g_sums)[(size_t)n * 16 + kq];
            float inv = 1.0f / fmaxf(g_cnt[n], 1.0f);
            v.x *= inv; v.y *= inv; v.z *= inv; v.w *= inv;
        }
        xs2[(2 * kq + 0) * XS2_STRIDE + nn] = make_float2(v.x, v.y);
        xs2[(2 * kq + 1) * XS2_STRIDE + nn] = make_float2(v.z, v.w);
    }
    __syncthreads();

    // re-zero this tile's scratch — FULL rows: 64 nodes x 16 float4 = 1024 items
    {
        float4 z = make_float4(0.f, 0.f, 0.f, 0.f);
        #pragma unroll
        for (int s = 0; s < 4; s++) {
            int item = tid + 256 * s;             // 0..1023
            int n = tile + (item >> 4);
            if (n < N_NODES)
                reinterpret_cast<float4*>(g_sums)[(size_t)n * 16 + (item & 15)] = z;
        }
        if (tid < 64 && tile + tid < N_NODES) g_cnt[tile + tid] = 0.f;
    }

    // edge half of layer 1: FFMA2 over k-pairs
    #pragma unroll 4
    for (int k2 = 0; k2 < 32; k2++) {
        uint64_t w2 = *reinterpret_cast<const uint64_t*>(&sW1b[k2 * 32 + lane]);
        const uint64_t* xr =
            reinterpret_cast<const uint64_t*>(&xs2[k2 * XS2_STRIDE + p * 8]);
        #pragma unroll
        for (int i = 0; i < 8; i++) ffma2(a2[i], xr[i], w2);
    }
    __syncthreads();   // xs2 reads done; reuse as h buffer

    // relu, park h j-major
    float* hs2 = reinterpret_cast<float*>(xs2);
    float h[8];
    #pragma unroll
    for (int i = 0; i < 8; i++) {
        float lo, hi; unpack2(a2[i], lo, hi);
        h[i] = fmaxf(lo + hi, 0.f);
    }
    #pragma unroll
    for (int q = 0; q < 4; q++)
        *reinterpret_cast<uint64_t*>(
            &hs2[lane * (2 * XS2_STRIDE) + p * 8 + 2 * q]) =
            pack2(h[2 * q], h[2 * q + 1]);
    __syncthreads();

    // layer 2
    uint64_t o2[4][2];
    #pragma unroll
    for (int q = 0; q < 4; q++) {
        o2[q][0] = pack2(sb2[lane], sb2[lane]);
        o2[q][1] = pack2(sb2[lane + 32], sb2[lane + 32]);
    }
    #pragma unroll 4
    for (int j = 0; j < LATENT; j++) {
        float wa = sW2[j * OUT_DIM + lane];
        float wb = sW2[j * OUT_DIM + lane + 32];
        uint64_t w0 = pack2(wa, wa);
        uint64_t w1 = pack2(wb, wb);
        const uint64_t* hr =
            reinterpret_cast<const uint64_t*>(&hs2[j * (2 * XS2_STRIDE) + p * 8]);
        #pragma unroll
        for (int q = 0; q < 4; q++) {
            uint64_t x = hr[q];
            ffma2(o2[q][0], x, w0);
            ffma2(o2[q][1], x, w1);
        }
    }

    #pragma unroll
    for (int q = 0; q < 4; q++) {
        int n0 = nbase + 2 * q;
        float a0, c0, a1, c1;
        unpack2(o2[q][0], a0, c0);
        unpack2(o2[q][1], a1, c1);
        if (n0 < N_NODES) {
            out[(size_t)n0 * OUT_DIM + lane]      = a0;
            out[(size_t)n0 * OUT_DIM + lane + 32] = a1;
        }
        if (n0 + 1 < N_NODES) {
            out[(size_t)(n0 + 1) * OUT_DIM + lane]      = c0;
            out[(size_t)(n0 + 1) * OUT_DIM + lane + 32] = c1;
        }
    }
}

// ---------------------------------------------------------------------------
extern "C" void kernel_launch(void* const* d_in, const int* in_sizes, int n_in,
                              void* d_out, int out_size) {
    const float* node_attr   = (const float*)d_in[0];
    const float* edge_attr   = (const float*)d_in[1];
    const float* global_attr = (const float*)d_in[2];
    const float* W1          = (const float*)d_in[3];
    const float* b1          = (const float*)d_in[4];
    const float* W2          = (const float*)d_in[5];
    const float* b2          = (const float*)d_in[6];
    const int*   recv        = (const int*)d_in[7];
    const int*   ng          = (const int*)d_in[8];
    float* out = (float*)d_out;

    // A) batched edge scatter + node projection + G
    scatter_kernel<<<SC_BLOCKS + NB_NODE + 1, 256>>>(edge_attr, recv, node_attr,
                                                     global_attr, W1, b1);

    // B) mean + edge-half layer1 + relu + layer2 (+ scratch re-zero)
    mlp_kernel<<<(N_NODES + 63) / 64, 256>>>(W1, W2, b2, ng, out);
}